// round 16
// baseline (speedup 1.0000x reference)
#include <cuda_runtime.h>
#include <cstdint>

// ---------------- problem dims ----------------
#define BB 4
#define NN 1024
#define DD 1024
#define HH 16
#define HD 64
#define ROWS (BB*NN)      // 4096
#define QKVN (3*DD)       // 3072
#define L2E 1.4426950408889634f

// ---------------- scratch ----------------
__device__ float    g_gamma[BB*DD];
__device__ float    g_beta[BB*DD];
__device__ uint16_t g_hb[ROWS*DD];          // SLN(hidden), bf16
__device__ uint16_t g_wqkvb[QKVN*DD];       // Wqkv bf16, pre-permuted rows
__device__ uint16_t g_wpb[DD*DD];           // Wp bf16
__device__ uint16_t g_qb[BB*HH*NN*HD];      // [bh][n][d], pre-scaled by log2e
__device__ uint16_t g_kb[BB*HH*NN*HD];      // [bh][n][d]
__device__ uint16_t g_vb[BB*HH*NN*HD];      // [bh][n][d]  (row-major V)
__device__ uint16_t g_aob[ROWS*DD];         // attention out bf16
__device__ float    g_h1[ROWS*DD];

// ================= helpers =================
__device__ __forceinline__ uint32_t smem_u32(const void* p) {
    uint32_t a;
    asm("{ .reg .u64 t; cvta.to.shared.u64 t, %1; cvt.u32.u64 %0, t; }"
        : "=r"(a) : "l"(p));
    return a;
}
__device__ __forceinline__ void cp16(uint32_t dst, const void* src) {
    asm volatile("cp.async.cg.shared.global [%0], [%1], 16;"
                 :: "r"(dst), "l"(src) : "memory");
}
__device__ __forceinline__ void cp_commit() {
    asm volatile("cp.async.commit_group;" ::: "memory");
}
template<int N>
__device__ __forceinline__ void cp_wait() {
    asm volatile("cp.async.wait_group %0;" :: "n"(N) : "memory");
}
__device__ __forceinline__ uint32_t pbf2(float lo, float hi) {
    uint32_t r;
    asm("cvt.rn.bf16x2.f32 %0, %1, %2;" : "=r"(r) : "f"(hi), "f"(lo));
    return r;
}
__device__ __forceinline__ float ex2f(float x) {
    float r; asm("ex2.approx.f32 %0, %1;" : "=f"(r) : "f"(x)); return r;
}
__device__ __forceinline__ void mma_bf16(float* d, const uint32_t* a,
                                         uint32_t b0, uint32_t b1) {
    asm volatile("mma.sync.aligned.m16n8k16.row.col.f32.bf16.bf16.f32 "
        "{%0,%1,%2,%3}, {%4,%5,%6,%7}, {%8,%9}, {%0,%1,%2,%3};"
        : "+f"(d[0]), "+f"(d[1]), "+f"(d[2]), "+f"(d[3])
        : "r"(a[0]), "r"(a[1]), "r"(a[2]), "r"(a[3]), "r"(b0), "r"(b1));
}
__device__ __forceinline__ void ldsm4(uint32_t& r0, uint32_t& r1,
                                      uint32_t& r2, uint32_t& r3, uint32_t a) {
    asm volatile("ldmatrix.sync.aligned.m8n8.x4.shared.b16 {%0,%1,%2,%3}, [%4];"
        : "=r"(r0), "=r"(r1), "=r"(r2), "=r"(r3) : "r"(a));
}
__device__ __forceinline__ void ldsm4t(uint32_t& r0, uint32_t& r1,
                                       uint32_t& r2, uint32_t& r3, uint32_t a) {
    asm volatile("ldmatrix.sync.aligned.m8n8.x4.trans.shared.b16 {%0,%1,%2,%3}, [%4];"
        : "=r"(r0), "=r"(r1), "=r"(r2), "=r"(r3) : "r"(a));
}
__device__ __forceinline__ void ldsm2t(uint32_t& r0, uint32_t& r1, uint32_t a) {
    asm volatile("ldmatrix.sync.aligned.m8n8.x2.trans.shared.b16 {%0,%1}, [%2];"
        : "=r"(r0), "=r"(r1) : "r"(a));
}

// ========== fused prep: weight conversion + gamma/beta GEMV ==========
__global__ void __launch_bounds__(256) prep_kernel(
    const float* __restrict__ Wqkv, const float* __restrict__ Wp,
    const float* __restrict__ w,  const float* __restrict__ Wg,
    const float* __restrict__ bg, const float* __restrict__ Wb,
    const float* __restrict__ bb)
{
    if (blockIdx.x < 4096) {
        int e = (blockIdx.x * 256 + threadIdx.x) * 4;
        if (e < QKVN * DD) {
            int j = e >> 10, k = e & 1023;
            int pj = ((j & 1023) >> 6) * 192 + (j & 63) * 3 + (j >> 10);
            float4 v = *(const float4*)(Wqkv + (size_t)pj * DD + k);
            *(uint2*)(g_wqkvb + e) = make_uint2(pbf2(v.x, v.y), pbf2(v.z, v.w));
        } else {
            int e2 = e - QKVN * DD;
            float4 v = *(const float4*)(Wp + e2);
            *(uint2*)(g_wpb + e2) = make_uint2(pbf2(v.x, v.y), pbf2(v.z, v.w));
        }
    } else {
        int lane = threadIdx.x & 31;
        int warp = threadIdx.x >> 5;
        int gid  = (blockIdx.x - 4096) * 8 + warp;
        int b = gid >> 10, d = gid & 1023;
        const float* wrow = w  + b * DD;
        const float* wg   = Wg + (size_t)d * DD;
        const float* wb   = Wb + (size_t)d * DD;
        float sg = 0.f, sb = 0.f;
        #pragma unroll
        for (int it = 0; it < 8; it++) {
            int k = it * 128 + lane * 4;
            float4 wk = *(const float4*)(wrow + k);
            float4 a  = *(const float4*)(wg + k);
            float4 c  = *(const float4*)(wb + k);
            sg = fmaf(wk.x, a.x, fmaf(wk.y, a.y, fmaf(wk.z, a.z, fmaf(wk.w, a.w, sg))));
            sb = fmaf(wk.x, c.x, fmaf(wk.y, c.y, fmaf(wk.z, c.z, fmaf(wk.w, c.w, sb))));
        }
        #pragma unroll
        for (int o = 16; o; o >>= 1) {
            sg += __shfl_xor_sync(0xffffffffu, sg, o);
            sb += __shfl_xor_sync(0xffffffffu, sb, o);
        }
        if (!lane) {
            g_gamma[gid] = sg + bg[d];
            g_beta[gid]  = sb + bb[d];
        }
    }
}

// =====================================================================
// bf16 GEMM: mma.m16n8k16, 4-stage cp.async ring (wait_group<2>), K=32
// per stage, ldmatrix frags.  (R8 mainloop — best measured config.)
// =====================================================================
#define MSTB 40
#define MM_STAGE (128 * MSTB)
#define MM_SBYTES (MM_STAGE * 2)              // 10240 bytes
#define MM_NST 4
#define MM_DSMEM (2 * MM_NST * MM_SBYTES)     // 81920 bytes

template<int QKV>
__global__ void __launch_bounds__(256, 2) mm_bf(
    const float* __restrict__ bias, const float* __restrict__ resid)
{
    extern __shared__ uint16_t smb[];
    uint16_t* Abuf = smb;
    uint16_t* Bbuf = smb + MM_NST * MM_STAGE;

    const int tid = threadIdx.x, lane = tid & 31, wid = tid >> 5;
    const int bm = blockIdx.y * 128, bn = blockIdx.x * 128;
    const uint16_t* Asrc = QKV ? g_hb : g_aob;
    const uint16_t* Bsrc = QKV ? g_wqkvb : g_wpb;

    const int r = tid >> 1, hh = tid & 1;
    const uint16_t* aptr = Asrc + (size_t)(bm + r) * DD + hh * 16;
    const uint16_t* bptr = Bsrc + (size_t)(bn + r) * DD + hh * 16;
    uint32_t sA[MM_NST], sB[MM_NST];
    #pragma unroll
    for (int s = 0; s < MM_NST; s++) {
        sA[s] = smem_u32(Abuf + s * MM_STAGE + r * MSTB + hh * 16);
        sB[s] = smem_u32(Bbuf + s * MM_STAGE + r * MSTB + hh * 16);
    }

    const int wm = (wid & 1) * 64, wn = (wid >> 1) * 32;
    const int g = lane >> 2, cc = lane & 3, c2 = cc * 2;

    const uint32_t abase0 = smem_u32(Abuf);
    const uint32_t bbase0 = smem_u32(Bbuf);
    const uint32_t laneA = ((lane >> 3) & 1) * 640 + (lane & 7) * 80 +
                           ((lane >> 4) & 1) * 16 + wm * 80;
    const uint32_t laneB = ((lane >> 4) & 1) * 640 + (lane & 7) * 80 +
                           ((lane >> 3) & 1) * 16 + wn * 80;

    float acc[4][4][4];
    #pragma unroll
    for (int mt = 0; mt < 4; mt++)
        #pragma unroll
        for (int nt = 0; nt < 4; nt++)
            #pragma unroll
            for (int e = 0; e < 4; e++) acc[mt][nt][e] = 0.f;

    #pragma unroll
    for (int s = 0; s < 3; s++) {
        cp16(sA[s], aptr + s * 32);  cp16(sA[s] + 16, aptr + s * 32 + 8);
        cp16(sB[s], bptr + s * 32);  cp16(sB[s] + 16, bptr + s * 32 + 8);
        cp_commit();
    }

    for (int t = 0; t < 32; t++) {
        const int buf = t & 3;
        if (t < 30) cp_wait<2>(); else cp_wait<0>();
        __syncthreads();
        if (t + 3 < 32) {
            const int s = (t + 3) & 3;
            const uint16_t* ap = aptr + (t + 3) * 32;
            const uint16_t* bp = bptr + (t + 3) * 32;
            cp16(sA[s], ap);  cp16(sA[s] + 16, ap + 8);
            cp16(sB[s], bp);  cp16(sB[s] + 16, bp + 8);
            cp_commit();
        }
        const uint32_t aAddr = abase0 + buf * MM_SBYTES + laneA;
        const uint32_t bAddr = bbase0 + buf * MM_SBYTES + laneB;
        #pragma unroll
        for (int kc = 0; kc < 2; kc++) {
            uint32_t af[4][4], bfr[4][2];
            #pragma unroll
            for (int mt = 0; mt < 4; mt++)
                ldsm4(af[mt][0], af[mt][1], af[mt][2], af[mt][3],
                      aAddr + mt * 1280 + kc * 32);
            #pragma unroll
            for (int np = 0; np < 2; np++)
                ldsm4(bfr[2*np][0], bfr[2*np][1], bfr[2*np+1][0], bfr[2*np+1][1],
                      bAddr + np * 1280 + kc * 32);
            #pragma unroll
            for (int mt = 0; mt < 4; mt++)
                #pragma unroll
                for (int nt = 0; nt < 4; nt++)
                    mma_bf16(acc[mt][nt], af[mt], bfr[nt][0], bfr[nt][1]);
        }
    }

    // ---- epilogue ----
    #pragma unroll
    for (int mt = 0; mt < 4; mt++) {
        #pragma unroll
        for (int nt = 0; nt < 4; nt++) {
            int R0 = bm + wm + mt * 16 + g;
            int C  = bn + wn + nt * 8 + c2;
            float v00 = acc[mt][nt][0], v01 = acc[mt][nt][1];
            float v10 = acc[mt][nt][2], v11 = acc[mt][nt][3];
            if (QKV) {
                int arr = C >> 10, rem = C & 1023;
                int head = rem >> 6, dd = rem & 63;
                float bx = bias[head * 192 + dd * 3 + arr];
                float by = bias[head * 192 + (dd + 1) * 3 + arr];
                int b0 = R0 >> 10, n0 = R0 & 1023;
                uint16_t* dst = (arr == 0) ? g_qb : (arr == 1) ? g_kb : g_vb;
                float sc = (arr == 0) ? L2E : 1.0f;   // Q pre-scaled by log2e
                size_t base = ((size_t)(b0 * HH + head)) * NN;
                *(uint32_t*)(dst + (base + n0) * HD + dd) =
                    pbf2((v00 + bx) * sc, (v01 + by) * sc);
                *(uint32_t*)(dst + (base + n0 + 8) * HD + dd) =
                    pbf2((v10 + bx) * sc, (v11 + by) * sc);
            } else {
                float2 bb = *(const float2*)(bias + C);
                float2 h0 = *(const float2*)(resid + (size_t)R0 * DD + C);
                float2 h1 = *(const float2*)(resid + (size_t)(R0 + 8) * DD + C);
                *(float2*)&g_h1[(size_t)R0 * DD + C] =
                    make_float2(v00 + bb.x + h0.x, v01 + bb.y + h0.y);
                *(float2*)&g_h1[(size_t)(R0 + 8) * DD + C] =
                    make_float2(v10 + bb.x + h1.x, v11 + bb.y + h1.y);
            }
        }
    }
}

// =====================================================================
// Flash attention, bf16 m16n8k16, 2-stage ring, exp2-domain softmax,
// row-sums via a ones-column in V (PV n-tile 8 accumulates l in TMEM-
// style accumulator; no rs adds/shuffles on the critical path).
// =====================================================================
#define AT_STAGE (64 * 72)
#define AT_SBYTES (AT_STAGE * 2)              // 9216 bytes
#define AT_DSMEM (4 * AT_SBYTES)              // 36864 bytes

__global__ void __launch_bounds__(256, 2) attn_bf()
{
    extern __shared__ uint16_t sma[];
    uint16_t* Ksb = sma;
    uint16_t* Vsb = sma + 2 * AT_STAGE;

    const int tid = threadIdx.x, lane = tid & 31, w = tid >> 5;
    const int g = lane >> 2, cc = lane & 3, c2 = cc * 2;
    const int bh = blockIdx.y, qt = blockIdx.x;

    const uint16_t* Kg = g_kb + (size_t)bh * NN * HD;
    const uint16_t* Vg = g_vb + (size_t)bh * NN * HD;

    const int lrow = tid >> 2;
    const int lcq  = (tid & 3) * 16;
    const uint16_t* kpb = Kg + lrow * HD + lcq;
    const uint16_t* vpb = Vg + lrow * HD + lcq;
    uint32_t skb[2], svb[2];
    #pragma unroll
    for (int s = 0; s < 2; s++) {
        skb[s] = smem_u32(Ksb + s * AT_STAGE + lrow * 72 + lcq);
        svb[s] = smem_u32(Vsb + s * AT_STAGE + lrow * 72 + lcq);
    }

    const uint32_t lmoff = ((lane >> 4) & 1) * 1152 + (lane & 7) * 144 +
                           ((lane >> 3) & 1) * 16;
    const uint32_t kfb0 = smem_u32(Ksb) + lmoff;
    const uint32_t vfb0 = smem_u32(Vsb) + lmoff;
    // ones-column ldsm.x2 address: dims 64-71 (byte offset 128 in each row)
    const uint32_t lm2off = (lane & 7) * 144 + ((lane >> 3) & 1) * 1152 + 128;
    const uint32_t vfb2_0 = smem_u32(Vsb) + lm2off;

    // seed pad columns of BOTH V buffers: col64 = bf16(1.0), cols65-71 = 0
    // (cp.async only writes bytes [0,128) of each 144B row, so this persists)
    if (tid < 128) {
        int bufi = tid >> 6, key = tid & 63;
        uint4 seed = make_uint4(0x00003f80u, 0u, 0u, 0u);
        *(uint4*)(Vsb + bufi * AT_STAGE + key * 72 + 64) = seed;
    }

    cp16(skb[0], kpb);  cp16(skb[0] + 16, kpb + 8);
    cp16(svb[0], vpb);  cp16(svb[0] + 16, vpb + 8);
    cp_commit();

    const uint32_t* Qg32 =
        (const uint32_t*)(g_qb + ((size_t)bh * NN + qt * 128 + w * 16) * HD);
    uint32_t qf[4][4];
    #pragma unroll
    for (int kc = 0; kc < 4; kc++) {
        qf[kc][0] = Qg32[g * 32 + kc * 8 + cc];
        qf[kc][1] = Qg32[(g + 8) * 32 + kc * 8 + cc];
        qf[kc][2] = Qg32[g * 32 + kc * 8 + cc + 4];
        qf[kc][3] = Qg32[(g + 8) * 32 + kc * 8 + cc + 4];
    }

    float o[8][4], o8[4];
    #pragma unroll
    for (int nt = 0; nt < 8; nt++)
        #pragma unroll
        for (int e = 0; e < 4; e++) o[nt][e] = 0.f;
    o8[0] = o8[1] = o8[2] = o8[3] = 0.f;
    float m0 = -1e30f, m1 = -1e30f;

    for (int t = 0; t < 16; t++) {
        const int buf = t & 1;
        cp_wait<0>();
        __syncthreads();          // also orders the pad-column seed (t==0)
        if (t < 15) {
            const uint16_t* kp = kpb + (size_t)(t + 1) * 64 * HD;
            const uint16_t* vp = vpb + (size_t)(t + 1) * 64 * HD;
            cp16(skb[buf ^ 1], kp);  cp16(skb[buf ^ 1] + 16, kp + 8);
            cp16(svb[buf ^ 1], vp);  cp16(svb[buf ^ 1] + 16, vp + 8);
            cp_commit();
        }
        const uint32_t kfA = kfb0 + buf * AT_SBYTES;
        const uint32_t vfA = vfb0 + buf * AT_SBYTES;
        const uint32_t vf2A = vfb2_0 + buf * AT_SBYTES;

        // ---- S = Q K^T  (log2 domain) ----
        float s[8][4];
        #pragma unroll
        for (int nt = 0; nt < 8; nt++)
            s[nt][0] = s[nt][1] = s[nt][2] = s[nt][3] = 0.f;
        #pragma unroll
        for (int np = 0; np < 4; np++) {
            #pragma unroll
            for (int kc = 0; kc < 4; kc++) {
                uint32_t t0, t1, t2, t3;
                ldsm4(t0, t1, t2, t3, kfA + np * 2304 + kc * 32);
                mma_bf16(s[2*np],     qf[kc], t0, t1);
                mma_bf16(s[2*np + 1], qf[kc], t2, t3);
            }
        }

        // ---- online softmax (base-2); row-sum handled by ones column ----
        float rmax0 = -1e30f, rmax1 = -1e30f;
        #pragma unroll
        for (int nt = 0; nt < 8; nt++) {
            rmax0 = fmaxf(rmax0, fmaxf(s[nt][0], s[nt][1]));
            rmax1 = fmaxf(rmax1, fmaxf(s[nt][2], s[nt][3]));
        }
        rmax0 = fmaxf(rmax0, __shfl_xor_sync(0xffffffffu, rmax0, 1));
        rmax0 = fmaxf(rmax0, __shfl_xor_sync(0xffffffffu, rmax0, 2));
        rmax1 = fmaxf(rmax1, __shfl_xor_sync(0xffffffffu, rmax1, 1));
        rmax1 = fmaxf(rmax1, __shfl_xor_sync(0xffffffffu, rmax1, 2));
        float mn0 = fmaxf(m0, rmax0), mn1 = fmaxf(m1, rmax1);
        float sc0 = ex2f(m0 - mn0), sc1 = ex2f(m1 - mn1);
        m0 = mn0; m1 = mn1;
        #pragma unroll
        for (int nt = 0; nt < 8; nt++) {
            s[nt][0] = ex2f(s[nt][0] - mn0);
            s[nt][1] = ex2f(s[nt][1] - mn0);
            s[nt][2] = ex2f(s[nt][2] - mn1);
            s[nt][3] = ex2f(s[nt][3] - mn1);
        }
        #pragma unroll
        for (int nt = 0; nt < 8; nt++) {
            o[nt][0] *= sc0; o[nt][1] *= sc0;
            o[nt][2] *= sc1; o[nt][3] *= sc1;
        }
        o8[0] *= sc0; o8[1] *= sc0; o8[2] *= sc1; o8[3] *= sc1;

        // ---- P: C-frag -> bf16 A-frag (register-only) ----
        uint32_t pa[4][4];
        #pragma unroll
        for (int kc = 0; kc < 4; kc++) {
            pa[kc][0] = pbf2(s[2 * kc][0],     s[2 * kc][1]);
            pa[kc][1] = pbf2(s[2 * kc][2],     s[2 * kc][3]);
            pa[kc][2] = pbf2(s[2 * kc + 1][0], s[2 * kc + 1][1]);
            pa[kc][3] = pbf2(s[2 * kc + 1][2], s[2 * kc + 1][3]);
        }

        // ---- O += P V ---- (ldmatrix.trans on row-major V tile)
        #pragma unroll
        for (int np = 0; np < 4; np++) {
            #pragma unroll
            for (int kc = 0; kc < 4; kc++) {
                uint32_t t0, t1, t2, t3;
                ldsm4t(t0, t1, t2, t3, vfA + kc * 2304 + np * 32);
                mma_bf16(o[2*np],     pa[kc], t0, t2);
                mma_bf16(o[2*np + 1], pa[kc], t1, t3);
            }
        }
        // ---- l += P · ones  (cols 64-71; col 64 is the ones column) ----
        #pragma unroll
        for (int kc = 0; kc < 4; kc++) {
            uint32_t u0, u1;
            ldsm2t(u0, u1, vf2A + kc * 2304);
            mma_bf16(o8, pa[kc], u0, u1);
        }
    }

    // ---- l lives in col 64 (owned by cc==0 lanes); broadcast in quad ----
    const int qsrc = lane & ~3;
    float l0 = __shfl_sync(0xffffffffu, o8[0], qsrc);
    float l1 = __shfl_sync(0xffffffffu, o8[2], qsrc);

    // ---- output: bf16(o / (l * 32)) -> g_aob ----
    const int b = bh >> 4, head = bh & 15;
    const int row0 = qt * 128 + w * 16 + g;
    float inv0 = 1.0f / (l0 * 32.0f);
    float inv1 = 1.0f / (l1 * 32.0f);
    uint32_t* d0 = (uint32_t*)(g_aob + ((size_t)b * NN + row0) * DD + head * HD);
    uint32_t* d1 = (uint32_t*)(g_aob + ((size_t)b * NN + row0 + 8) * DD + head * HD);
    #pragma unroll
    for (int nt = 0; nt < 8; nt++) {
        d0[nt * 4 + cc] = pbf2(o[nt][0] * inv0, o[nt][1] * inv0);
        d1[nt * 4 + cc] = pbf2(o[nt][2] * inv1, o[nt][3] * inv1);
    }
}

// ================= SLN kernels: 2 rows/block =================
__global__ void __launch_bounds__(256) sln1_kernel(
    const float* __restrict__ x, const float* __restrict__ ln_g,
    const float* __restrict__ ln_b)
{
    __shared__ float red[16];
    const int rl = threadIdx.x >> 7;
    const int li = threadIdx.x & 127;
    const int row = blockIdx.x * 2 + rl;
    const int b = row >> 10;
    const int d = li * 8;
    const float* xr = x + (size_t)row * DD + d;
    float4 x0 = *(const float4*)(xr);
    float4 x1 = *(const float4*)(xr + 4);
    float s = x0.x + x0.y + x0.z + x0.w + x1.x + x1.y + x1.z + x1.w;
    float q = x0.x*x0.x + x0.y*x0.y + x0.z*x0.z + x0.w*x0.w
            + x1.x*x1.x + x1.y*x1.y + x1.z*x1.z + x1.w*x1.w;
    #pragma unroll
    for (int o = 16; o; o >>= 1) {
        s += __shfl_xor_sync(0xffffffffu, s, o);
        q += __shfl_xor_sync(0xffffffffu, q, o);
    }
    int warp = threadIdx.x >> 5, lane = threadIdx.x & 31;
    if (!lane) { red[warp] = s; red[8 + warp] = q; }
    __syncthreads();
    float ss = red[rl*4] + red[rl*4+1] + red[rl*4+2] + red[rl*4+3];
    float qq = red[8+rl*4] + red[8+rl*4+1] + red[8+rl*4+2] + red[8+rl*4+3];
    float mu = ss * (1.0f / DD);
    float rstd = rsqrtf(qq * (1.0f / DD) - mu * mu + 1e-5f);

    float4 g0  = *(const float4*)(ln_g + d);
    float4 g1  = *(const float4*)(ln_g + d + 4);
    float4 lb0 = *(const float4*)(ln_b + d);
    float4 lb1 = *(const float4*)(ln_b + d + 4);
    float4 ga0 = *(const float4*)(g_gamma + b * DD + d);
    float4 ga1 = *(const float4*)(g_gamma + b * DD + d + 4);
    float4 be0 = *(const float4*)(g_beta  + b * DD + d);
    float4 be1 = *(const float4*)(g_beta  + b * DD + d + 4);
    float y0 = fmaf(ga0.x, fmaf((x0.x - mu) * rstd, g0.x, lb0.x), be0.x);
    float y1 = fmaf(ga0.y, fmaf((x0.y - mu) * rstd, g0.y, lb0.y), be0.y);
    float y2 = fmaf(ga0.z, fmaf((x0.z - mu) * rstd, g0.z, lb0.z), be0.z);
    float y3 = fmaf(ga0.w, fmaf((x0.w - mu) * rstd, g0.w, lb0.w), be0.w);
    float y4 = fmaf(ga1.x, fmaf((x1.x - mu) * rstd, g1.x, lb1.x), be1.x);
    float y5 = fmaf(ga1.y, fmaf((x1.y - mu) * rstd, g1.y, lb1.y), be1.y);
    float y6 = fmaf(ga1.z, fmaf((x1.z - mu) * rstd, g1.z, lb1.z), be1.z);
    float y7 = fmaf(ga1.w, fmaf((x1.w - mu) * rstd, g1.w, lb1.w), be1.w);
    uint4 pk = make_uint4(pbf2(y0, y1), pbf2(y2, y3), pbf2(y4, y5), pbf2(y6, y7));
    *(uint4*)(g_hb + (size_t)row * DD + d) = pk;
}

__global__ void __launch_bounds__(256) sln2_kernel(
    const float* __restrict__ ln_g, const float* __restrict__ ln_b,
    float* __restrict__ out)
{
    __shared__ float red[16];
    const int rl = threadIdx.x >> 7;
    const int li = threadIdx.x & 127;
    const int row = blockIdx.x * 2 + rl;
    const int b = row >> 10;
    const int d = li * 8;
    const float* xr = g_h1 + (size_t)row * DD + d;
    float4 x0 = *(const float4*)(xr);
    float4 x1 = *(const float4*)(xr + 4);
    float s = x0.x + x0.y + x0.z + x0.w + x1.x + x1.y + x1.z + x1.w;
    float q = x0.x*x0.x + x0.y*x0.y + x0.z*x0.z + x0.w*x0.w
            + x1.x*x1.x + x1.y*x1.y + x1.z*x1.z + x1.w*x1.w;
    #pragma unroll
    for (int o = 16; o; o >>= 1) {
        s += __shfl_xor_sync(0xffffffffu, s, o);
        q += __shfl_xor_sync(0xffffffffu, q, o);
    }
    int warp = threadIdx.x >> 5, lane = threadIdx.x & 31;
    if (!lane) { red[warp] = s; red[8 + warp] = q; }
    __syncthreads();
    float ss = red[rl*4] + red[rl*4+1] + red[rl*4+2] + red[rl*4+3];
    float qq = red[8+rl*4] + red[8+rl*4+1] + red[8+rl*4+2] + red[8+rl*4+3];
    float mu = ss * (1.0f / DD);
    float rstd = rsqrtf(qq * (1.0f / DD) - mu * mu + 1e-5f);

    float4 g0  = *(const float4*)(ln_g + d);
    float4 g1  = *(const float4*)(ln_g + d + 4);
    float4 lb0 = *(const float4*)(ln_b + d);
    float4 lb1 = *(const float4*)(ln_b + d + 4);
    float4 ga0 = *(const float4*)(g_gamma + b * DD + d);
    float4 ga1 = *(const float4*)(g_gamma + b * DD + d + 4);
    float4 be0 = *(const float4*)(g_beta  + b * DD + d);
    float4 be1 = *(const float4*)(g_beta  + b * DD + d + 4);
    float4 ya, yb;
    ya.x = fmaf(ga0.x, fmaf((x0.x - mu) * rstd, g0.x, lb0.x), be0.x) + x0.x;
    ya.y = fmaf(ga0.y, fmaf((x0.y - mu) * rstd, g0.y, lb0.y), be0.y) + x0.y;
    ya.z = fmaf(ga0.z, fmaf((x0.z - mu) * rstd, g0.z, lb0.z), be0.z) + x0.z;
    ya.w = fmaf(ga0.w, fmaf((x0.w - mu) * rstd, g0.w, lb0.w), be0.w) + x0.w;
    yb.x = fmaf(ga1.x, fmaf((x1.x - mu) * rstd, g1.x, lb1.x), be1.x) + x1.x;
    yb.y = fmaf(ga1.y, fmaf((x1.y - mu) * rstd, g1.y, lb1.y), be1.y) + x1.y;
    yb.z = fmaf(ga1.z, fmaf((x1.z - mu) * rstd, g1.z, lb1.z), be1.z) + x1.z;
    yb.w = fmaf(ga1.w, fmaf((x1.w - mu) * rstd, g1.w, lb1.w), be1.w) + x1.w;
    *(float4*)&out[(size_t)row * DD + d]     = ya;
    *(float4*)&out[(size_t)row * DD + d + 4] = yb;
}

// =====================================================================
extern "C" void kernel_launch(void* const* d_in, const int* in_sizes, int n_in,
                              void* d_out, int out_size)
{
    (void)in_sizes; (void)n_in; (void)out_size;
    const float* hidden = (const float*)d_in[0];
    const float* w      = (const float*)d_in[1];
    const float* ln_g   = (const float*)d_in[2];
    const float* ln_b   = (const float*)d_in[3];
    const float* Wg     = (const float*)d_in[4];
    const float* bg     = (const float*)d_in[5];
    const float* Wb     = (const float*)d_in[6];
    const float* bb     = (const float*)d_in[7];
    const float* Wqkv   = (const float*)d_in[8];
    const float* bqkv   = (const float*)d_in[9];
    const float* Wp     = (const float*)d_in[10];
    const float* bp     = (const float*)d_in[11];
    float* out = (float*)d_out;

    cudaFuncSetAttribute(mm_bf<1>, cudaFuncAttributeMaxDynamicSharedMemorySize, MM_DSMEM);
    cudaFuncSetAttribute(mm_bf<0>, cudaFuncAttributeMaxDynamicSharedMemorySize, MM_DSMEM);
    cudaFuncSetAttribute(attn_bf, cudaFuncAttributeMaxDynamicSharedMemorySize, AT_DSMEM);

    prep_kernel<<<4608, 256>>>(Wqkv, Wp, w, Wg, bg, Wb, bb);
    sln1_kernel<<<ROWS / 2, 256>>>(hidden, ln_g, ln_b);
    mm_bf<1><<<dim3(QKVN / 128, ROWS / 128), 256, MM_DSMEM>>>(bqkv, hidden);
    attn_bf<<<dim3(NN / 128, BB * HH), 256, AT_DSMEM>>>();
    mm_bf<0><<<dim3(DD / 128, ROWS / 128), 256, MM_DSMEM>>>(bp, hidden);
    sln2_kernel<<<ROWS / 2, 256>>>(ln_g, ln_b, out);
}

// round 17
// speedup vs baseline: 1.0167x; 1.0167x over previous
#include <cuda_runtime.h>
#include <cstdint>

// ---------------- problem dims ----------------
#define BB 4
#define NN 1024
#define DD 1024
#define HH 16
#define HD 64
#define ROWS (BB*NN)      // 4096
#define QKVN (3*DD)       // 3072
#define L2E 1.4426950408889634f

// ---------------- scratch ----------------
__device__ float    g_gamma[BB*DD];
__device__ float    g_beta[BB*DD];
__device__ uint16_t g_hb[ROWS*DD];          // SLN(hidden), bf16
__device__ uint16_t g_wqkvb[QKVN*DD];       // Wqkv bf16, pre-permuted rows
__device__ uint16_t g_wpb[DD*DD];           // Wp bf16
__device__ uint16_t g_qb[BB*HH*NN*HD];      // [bh][n][d], pre-scaled by log2e
__device__ uint16_t g_kb[BB*HH*NN*HD];      // [bh][n][d]
__device__ uint16_t g_vb[BB*HH*NN*HD];      // [bh][n][d]  (row-major V)
__device__ uint16_t g_aob[ROWS*DD];         // attention out bf16
__device__ float    g_h1[ROWS*DD];

// ================= helpers =================
__device__ __forceinline__ uint32_t smem_u32(const void* p) {
    uint32_t a;
    asm("{ .reg .u64 t; cvta.to.shared.u64 t, %1; cvt.u32.u64 %0, t; }"
        : "=r"(a) : "l"(p));
    return a;
}
__device__ __forceinline__ void cp16(uint32_t dst, const void* src) {
    asm volatile("cp.async.cg.shared.global [%0], [%1], 16;"
                 :: "r"(dst), "l"(src) : "memory");
}
__device__ __forceinline__ void cp_commit() {
    asm volatile("cp.async.commit_group;" ::: "memory");
}
template<int N>
__device__ __forceinline__ void cp_wait() {
    asm volatile("cp.async.wait_group %0;" :: "n"(N) : "memory");
}
__device__ __forceinline__ uint32_t pbf2(float lo, float hi) {
    uint32_t r;
    asm("cvt.rn.bf16x2.f32 %0, %1, %2;" : "=r"(r) : "f"(hi), "f"(lo));
    return r;
}
__device__ __forceinline__ float ex2f(float x) {
    float r; asm("ex2.approx.f32 %0, %1;" : "=f"(r) : "f"(x)); return r;
}
__device__ __forceinline__ void mma_bf16(float* d, const uint32_t* a,
                                         uint32_t b0, uint32_t b1) {
    asm volatile("mma.sync.aligned.m16n8k16.row.col.f32.bf16.bf16.f32 "
        "{%0,%1,%2,%3}, {%4,%5,%6,%7}, {%8,%9}, {%0,%1,%2,%3};"
        : "+f"(d[0]), "+f"(d[1]), "+f"(d[2]), "+f"(d[3])
        : "r"(a[0]), "r"(a[1]), "r"(a[2]), "r"(a[3]), "r"(b0), "r"(b1));
}
__device__ __forceinline__ void ldsm4(uint32_t& r0, uint32_t& r1,
                                      uint32_t& r2, uint32_t& r3, uint32_t a) {
    asm volatile("ldmatrix.sync.aligned.m8n8.x4.shared.b16 {%0,%1,%2,%3}, [%4];"
        : "=r"(r0), "=r"(r1), "=r"(r2), "=r"(r3) : "r"(a));
}
__device__ __forceinline__ void ldsm4t(uint32_t& r0, uint32_t& r1,
                                       uint32_t& r2, uint32_t& r3, uint32_t a) {
    asm volatile("ldmatrix.sync.aligned.m8n8.x4.trans.shared.b16 {%0,%1,%2,%3}, [%4];"
        : "=r"(r0), "=r"(r1), "=r"(r2), "=r"(r3) : "r"(a));
}

// ========== fused prep: weight conversion + gamma/beta GEMV ==========
__global__ void __launch_bounds__(256) prep_kernel(
    const float* __restrict__ Wqkv, const float* __restrict__ Wp,
    const float* __restrict__ w,  const float* __restrict__ Wg,
    const float* __restrict__ bg, const float* __restrict__ Wb,
    const float* __restrict__ bb)
{
    if (blockIdx.x < 4096) {
        int e = (blockIdx.x * 256 + threadIdx.x) * 4;
        if (e < QKVN * DD) {
            int j = e >> 10, k = e & 1023;
            int pj = ((j & 1023) >> 6) * 192 + (j & 63) * 3 + (j >> 10);
            float4 v = *(const float4*)(Wqkv + (size_t)pj * DD + k);
            *(uint2*)(g_wqkvb + e) = make_uint2(pbf2(v.x, v.y), pbf2(v.z, v.w));
        } else {
            int e2 = e - QKVN * DD;
            float4 v = *(const float4*)(Wp + e2);
            *(uint2*)(g_wpb + e2) = make_uint2(pbf2(v.x, v.y), pbf2(v.z, v.w));
        }
    } else {
        int lane = threadIdx.x & 31;
        int warp = threadIdx.x >> 5;
        int gid  = (blockIdx.x - 4096) * 8 + warp;
        int b = gid >> 10, d = gid & 1023;
        const float* wrow = w  + b * DD;
        const float* wg   = Wg + (size_t)d * DD;
        const float* wb   = Wb + (size_t)d * DD;
        float sg = 0.f, sb = 0.f;
        #pragma unroll
        for (int it = 0; it < 8; it++) {
            int k = it * 128 + lane * 4;
            float4 wk = *(const float4*)(wrow + k);
            float4 a  = *(const float4*)(wg + k);
            float4 c  = *(const float4*)(wb + k);
            sg = fmaf(wk.x, a.x, fmaf(wk.y, a.y, fmaf(wk.z, a.z, fmaf(wk.w, a.w, sg))));
            sb = fmaf(wk.x, c.x, fmaf(wk.y, c.y, fmaf(wk.z, c.z, fmaf(wk.w, c.w, sb))));
        }
        #pragma unroll
        for (int o = 16; o; o >>= 1) {
            sg += __shfl_xor_sync(0xffffffffu, sg, o);
            sb += __shfl_xor_sync(0xffffffffu, sb, o);
        }
        if (!lane) {
            g_gamma[gid] = sg + bg[d];
            g_beta[gid]  = sb + bb[d];
        }
    }
}

// =====================================================================
// bf16 GEMM: mma.m16n8k16, 4-stage cp.async ring (wait_group<2>), K=32
// per stage, ldmatrix frags.  (R8 mainloop — best measured config.)
// =====================================================================
#define MSTB 40
#define MM_STAGE (128 * MSTB)
#define MM_SBYTES (MM_STAGE * 2)              // 10240 bytes
#define MM_NST 4
#define MM_DSMEM (2 * MM_NST * MM_SBYTES)     // 81920 bytes

template<int QKV>
__global__ void __launch_bounds__(256, 2) mm_bf(
    const float* __restrict__ bias, const float* __restrict__ resid)
{
    extern __shared__ uint16_t smb[];
    uint16_t* Abuf = smb;
    uint16_t* Bbuf = smb + MM_NST * MM_STAGE;

    const int tid = threadIdx.x, lane = tid & 31, wid = tid >> 5;
    const int bm = blockIdx.y * 128, bn = blockIdx.x * 128;
    const uint16_t* Asrc = QKV ? g_hb : g_aob;
    const uint16_t* Bsrc = QKV ? g_wqkvb : g_wpb;

    const int r = tid >> 1, hh = tid & 1;
    const uint16_t* aptr = Asrc + (size_t)(bm + r) * DD + hh * 16;
    const uint16_t* bptr = Bsrc + (size_t)(bn + r) * DD + hh * 16;
    uint32_t sA[MM_NST], sB[MM_NST];
    #pragma unroll
    for (int s = 0; s < MM_NST; s++) {
        sA[s] = smem_u32(Abuf + s * MM_STAGE + r * MSTB + hh * 16);
        sB[s] = smem_u32(Bbuf + s * MM_STAGE + r * MSTB + hh * 16);
    }

    const int wm = (wid & 1) * 64, wn = (wid >> 1) * 32;
    const int g = lane >> 2, cc = lane & 3, c2 = cc * 2;

    const uint32_t abase0 = smem_u32(Abuf);
    const uint32_t bbase0 = smem_u32(Bbuf);
    const uint32_t laneA = ((lane >> 3) & 1) * 640 + (lane & 7) * 80 +
                           ((lane >> 4) & 1) * 16 + wm * 80;
    const uint32_t laneB = ((lane >> 4) & 1) * 640 + (lane & 7) * 80 +
                           ((lane >> 3) & 1) * 16 + wn * 80;

    float acc[4][4][4];
    #pragma unroll
    for (int mt = 0; mt < 4; mt++)
        #pragma unroll
        for (int nt = 0; nt < 4; nt++)
            #pragma unroll
            for (int e = 0; e < 4; e++) acc[mt][nt][e] = 0.f;

    #pragma unroll
    for (int s = 0; s < 3; s++) {
        cp16(sA[s], aptr + s * 32);  cp16(sA[s] + 16, aptr + s * 32 + 8);
        cp16(sB[s], bptr + s * 32);  cp16(sB[s] + 16, bptr + s * 32 + 8);
        cp_commit();
    }

    for (int t = 0; t < 32; t++) {
        const int buf = t & 3;
        if (t < 30) cp_wait<2>(); else cp_wait<0>();
        __syncthreads();
        if (t + 3 < 32) {
            const int s = (t + 3) & 3;
            const uint16_t* ap = aptr + (t + 3) * 32;
            const uint16_t* bp = bptr + (t + 3) * 32;
            cp16(sA[s], ap);  cp16(sA[s] + 16, ap + 8);
            cp16(sB[s], bp);  cp16(sB[s] + 16, bp + 8);
            cp_commit();
        }
        const uint32_t aAddr = abase0 + buf * MM_SBYTES + laneA;
        const uint32_t bAddr = bbase0 + buf * MM_SBYTES + laneB;
        #pragma unroll
        for (int kc = 0; kc < 2; kc++) {
            uint32_t af[4][4], bfr[4][2];
            #pragma unroll
            for (int mt = 0; mt < 4; mt++)
                ldsm4(af[mt][0], af[mt][1], af[mt][2], af[mt][3],
                      aAddr + mt * 1280 + kc * 32);
            #pragma unroll
            for (int np = 0; np < 2; np++)
                ldsm4(bfr[2*np][0], bfr[2*np][1], bfr[2*np+1][0], bfr[2*np+1][1],
                      bAddr + np * 1280 + kc * 32);
            #pragma unroll
            for (int mt = 0; mt < 4; mt++)
                #pragma unroll
                for (int nt = 0; nt < 4; nt++)
                    mma_bf16(acc[mt][nt], af[mt], bfr[nt][0], bfr[nt][1]);
        }
    }

    // ---- epilogue ----
    #pragma unroll
    for (int mt = 0; mt < 4; mt++) {
        #pragma unroll
        for (int nt = 0; nt < 4; nt++) {
            int R0 = bm + wm + mt * 16 + g;
            int C  = bn + wn + nt * 8 + c2;
            float v00 = acc[mt][nt][0], v01 = acc[mt][nt][1];
            float v10 = acc[mt][nt][2], v11 = acc[mt][nt][3];
            if (QKV) {
                int arr = C >> 10, rem = C & 1023;
                int head = rem >> 6, dd = rem & 63;
                float bx = bias[head * 192 + dd * 3 + arr];
                float by = bias[head * 192 + (dd + 1) * 3 + arr];
                int b0 = R0 >> 10, n0 = R0 & 1023;
                uint16_t* dst = (arr == 0) ? g_qb : (arr == 1) ? g_kb : g_vb;
                float sc = (arr == 0) ? L2E : 1.0f;   // Q pre-scaled by log2e
                size_t base = ((size_t)(b0 * HH + head)) * NN;
                *(uint32_t*)(dst + (base + n0) * HD + dd) =
                    pbf2((v00 + bx) * sc, (v01 + by) * sc);
                *(uint32_t*)(dst + (base + n0 + 8) * HD + dd) =
                    pbf2((v10 + bx) * sc, (v11 + by) * sc);
            } else {
                float2 bb = *(const float2*)(bias + C);
                float2 h0 = *(const float2*)(resid + (size_t)R0 * DD + C);
                float2 h1 = *(const float2*)(resid + (size_t)(R0 + 8) * DD + C);
                *(float2*)&g_h1[(size_t)R0 * DD + C] =
                    make_float2(v00 + bb.x + h0.x, v01 + bb.y + h0.y);
                *(float2*)&g_h1[(size_t)(R0 + 8) * DD + C] =
                    make_float2(v10 + bb.x + h1.x, v11 + bb.y + h1.y);
            }
        }
    }
}

// =====================================================================
// Flash attention, bf16 m16n8k16, 2-stage ring, exp2-domain softmax
// (Q pre-scaled by log2e; all exps are bare ex2.approx).
// =====================================================================
#define AT_STAGE (64 * 72)
#define AT_SBYTES (AT_STAGE * 2)              // 9216 bytes
#define AT_DSMEM (4 * AT_SBYTES)              // 36864 bytes

__global__ void __launch_bounds__(256, 2) attn_bf()
{
    extern __shared__ uint16_t sma[];
    uint16_t* Ksb = sma;
    uint16_t* Vsb = sma + 2 * AT_STAGE;

    const int tid = threadIdx.x, lane = tid & 31, w = tid >> 5;
    const int g = lane >> 2, cc = lane & 3, c2 = cc * 2;
    const int bh = blockIdx.y, qt = blockIdx.x;

    const uint16_t* Kg = g_kb + (size_t)bh * NN * HD;
    const uint16_t* Vg = g_vb + (size_t)bh * NN * HD;

    const int lrow = tid >> 2;
    const int lcq  = (tid & 3) * 16;
    const uint16_t* kpb = Kg + lrow * HD + lcq;
    const uint16_t* vpb = Vg + lrow * HD + lcq;
    uint32_t skb[2], svb[2];
    #pragma unroll
    for (int s = 0; s < 2; s++) {
        skb[s] = smem_u32(Ksb + s * AT_STAGE + lrow * 72 + lcq);
        svb[s] = smem_u32(Vsb + s * AT_STAGE + lrow * 72 + lcq);
    }

    const uint32_t lmoff = ((lane >> 4) & 1) * 1152 + (lane & 7) * 144 +
                           ((lane >> 3) & 1) * 16;
    const uint32_t kfb0 = smem_u32(Ksb) + lmoff;
    const uint32_t vfb0 = smem_u32(Vsb) + lmoff;

    cp16(skb[0], kpb);  cp16(skb[0] + 16, kpb + 8);
    cp16(svb[0], vpb);  cp16(svb[0] + 16, vpb + 8);
    cp_commit();

    const uint32_t* Qg32 =
        (const uint32_t*)(g_qb + ((size_t)bh * NN + qt * 128 + w * 16) * HD);
    uint32_t qf[4][4];
    #pragma unroll
    for (int kc = 0; kc < 4; kc++) {
        qf[kc][0] = Qg32[g * 32 + kc * 8 + cc];
        qf[kc][1] = Qg32[(g + 8) * 32 + kc * 8 + cc];
        qf[kc][2] = Qg32[g * 32 + kc * 8 + cc + 4];
        qf[kc][3] = Qg32[(g + 8) * 32 + kc * 8 + cc + 4];
    }

    float o[8][4];
    #pragma unroll
    for (int nt = 0; nt < 8; nt++)
        #pragma unroll
        for (int e = 0; e < 4; e++) o[nt][e] = 0.f;
    float m0 = -1e30f, m1 = -1e30f, l0 = 0.f, l1 = 0.f;

    for (int t = 0; t < 16; t++) {
        const int buf = t & 1;
        cp_wait<0>();
        __syncthreads();
        if (t < 15) {
            const uint16_t* kp = kpb + (size_t)(t + 1) * 64 * HD;
            const uint16_t* vp = vpb + (size_t)(t + 1) * 64 * HD;
            cp16(skb[buf ^ 1], kp);  cp16(skb[buf ^ 1] + 16, kp + 8);
            cp16(svb[buf ^ 1], vp);  cp16(svb[buf ^ 1] + 16, vp + 8);
            cp_commit();
        }
        const uint32_t kfA = kfb0 + buf * AT_SBYTES;
        const uint32_t vfA = vfb0 + buf * AT_SBYTES;

        // ---- S = Q K^T  (log2 domain) ----
        float s[8][4];
        #pragma unroll
        for (int nt = 0; nt < 8; nt++)
            s[nt][0] = s[nt][1] = s[nt][2] = s[nt][3] = 0.f;
        #pragma unroll
        for (int np = 0; np < 4; np++) {
            #pragma unroll
            for (int kc = 0; kc < 4; kc++) {
                uint32_t t0, t1, t2, t3;
                ldsm4(t0, t1, t2, t3, kfA + np * 2304 + kc * 32);
                mma_bf16(s[2*np],     qf[kc], t0, t1);
                mma_bf16(s[2*np + 1], qf[kc], t2, t3);
            }
        }

        // ---- online softmax (base-2) ----
        float rmax0 = -1e30f, rmax1 = -1e30f;
        #pragma unroll
        for (int nt = 0; nt < 8; nt++) {
            rmax0 = fmaxf(rmax0, fmaxf(s[nt][0], s[nt][1]));
            rmax1 = fmaxf(rmax1, fmaxf(s[nt][2], s[nt][3]));
        }
        rmax0 = fmaxf(rmax0, __shfl_xor_sync(0xffffffffu, rmax0, 1));
        rmax0 = fmaxf(rmax0, __shfl_xor_sync(0xffffffffu, rmax0, 2));
        rmax1 = fmaxf(rmax1, __shfl_xor_sync(0xffffffffu, rmax1, 1));
        rmax1 = fmaxf(rmax1, __shfl_xor_sync(0xffffffffu, rmax1, 2));
        float mn0 = fmaxf(m0, rmax0), mn1 = fmaxf(m1, rmax1);
        float sc0 = ex2f(m0 - mn0), sc1 = ex2f(m1 - mn1);
        m0 = mn0; m1 = mn1;
        float rs0 = 0.f, rs1 = 0.f;
        #pragma unroll
        for (int nt = 0; nt < 8; nt++) {
            s[nt][0] = ex2f(s[nt][0] - mn0); rs0 += s[nt][0];
            s[nt][1] = ex2f(s[nt][1] - mn0); rs0 += s[nt][1];
            s[nt][2] = ex2f(s[nt][2] - mn1); rs1 += s[nt][2];
            s[nt][3] = ex2f(s[nt][3] - mn1); rs1 += s[nt][3];
        }
        rs0 += __shfl_xor_sync(0xffffffffu, rs0, 1);
        rs0 += __shfl_xor_sync(0xffffffffu, rs0, 2);
        rs1 += __shfl_xor_sync(0xffffffffu, rs1, 1);
        rs1 += __shfl_xor_sync(0xffffffffu, rs1, 2);
        l0 = l0 * sc0 + rs0;
        l1 = l1 * sc1 + rs1;
        #pragma unroll
        for (int nt = 0; nt < 8; nt++) {
            o[nt][0] *= sc0; o[nt][1] *= sc0;
            o[nt][2] *= sc1; o[nt][3] *= sc1;
        }

        // ---- P: C-frag -> bf16 A-frag (register-only) ----
        uint32_t pa[4][4];
        #pragma unroll
        for (int kc = 0; kc < 4; kc++) {
            pa[kc][0] = pbf2(s[2 * kc][0],     s[2 * kc][1]);
            pa[kc][1] = pbf2(s[2 * kc][2],     s[2 * kc][3]);
            pa[kc][2] = pbf2(s[2 * kc + 1][0], s[2 * kc + 1][1]);
            pa[kc][3] = pbf2(s[2 * kc + 1][2], s[2 * kc + 1][3]);
        }

        // ---- O += P V ---- (ldmatrix.trans on row-major V tile)
        #pragma unroll
        for (int np = 0; np < 4; np++) {
            #pragma unroll
            for (int kc = 0; kc < 4; kc++) {
                uint32_t t0, t1, t2, t3;
                ldsm4t(t0, t1, t2, t3, vfA + kc * 2304 + np * 32);
                mma_bf16(o[2*np],     pa[kc], t0, t2);
                mma_bf16(o[2*np + 1], pa[kc], t1, t3);
            }
        }
    }

    // ---- output: bf16(o / (l * 32)) -> g_aob ----
    const int b = bh >> 4, head = bh & 15;
    const int row0 = qt * 128 + w * 16 + g;
    float inv0 = 1.0f / (l0 * 32.0f);
    float inv1 = 1.0f / (l1 * 32.0f);
    uint32_t* d0 = (uint32_t*)(g_aob + ((size_t)b * NN + row0) * DD + head * HD);
    uint32_t* d1 = (uint32_t*)(g_aob + ((size_t)b * NN + row0 + 8) * DD + head * HD);
    #pragma unroll
    for (int nt = 0; nt < 8; nt++) {
        d0[nt * 4 + cc] = pbf2(o[nt][0] * inv0, o[nt][1] * inv0);
        d1[nt * 4 + cc] = pbf2(o[nt][2] * inv1, o[nt][3] * inv1);
    }
}

// ================= SLN kernels (R14 proven versions) =================
__device__ __forceinline__ void row_stats(float4 xv, float& mu, float& rstd,
                                          float* red)
{
    float s = xv.x + xv.y + xv.z + xv.w;
    float q = xv.x*xv.x + xv.y*xv.y + xv.z*xv.z + xv.w*xv.w;
    #pragma unroll
    for (int o = 16; o; o >>= 1) {
        s += __shfl_xor_sync(0xffffffffu, s, o);
        q += __shfl_xor_sync(0xffffffffu, q, o);
    }
    int warp = threadIdx.x >> 5, lane = threadIdx.x & 31;
    if (!lane) { red[warp] = s; red[8 + warp] = q; }
    __syncthreads();
    float ss = 0.f, qq = 0.f;
    #pragma unroll
    for (int i = 0; i < 8; i++) { ss += red[i]; qq += red[8 + i]; }
    mu = ss * (1.0f / DD);
    float var = qq * (1.0f / DD) - mu * mu;
    rstd = rsqrtf(var + 1e-5f);
}

__global__ void __launch_bounds__(256) sln1_kernel(
    const float* __restrict__ x, const float* __restrict__ ln_g,
    const float* __restrict__ ln_b)
{
    __shared__ float red[16];
    int row = blockIdx.x;
    int b = row >> 10;
    float4 xv = *(const float4*)(x + (size_t)row * DD + threadIdx.x * 4);
    float mu, rstd;
    row_stats(xv, mu, rstd, red);
    int d = threadIdx.x * 4;
    float4 g  = *(const float4*)(ln_g + d);
    float4 lb = *(const float4*)(ln_b + d);
    float4 ga = *(const float4*)(g_gamma + b * DD + d);
    float4 be = *(const float4*)(g_beta  + b * DD + d);
    float yx = fmaf(ga.x, fmaf((xv.x - mu) * rstd, g.x, lb.x), be.x);
    float yy = fmaf(ga.y, fmaf((xv.y - mu) * rstd, g.y, lb.y), be.y);
    float yz = fmaf(ga.z, fmaf((xv.z - mu) * rstd, g.z, lb.z), be.z);
    float yw = fmaf(ga.w, fmaf((xv.w - mu) * rstd, g.w, lb.w), be.w);
    *(uint2*)(g_hb + (size_t)row * DD + d) =
        make_uint2(pbf2(yx, yy), pbf2(yz, yw));
}

__global__ void __launch_bounds__(256) sln2_kernel(
    const float* __restrict__ ln_g, const float* __restrict__ ln_b,
    float* __restrict__ out)
{
    __shared__ float red[16];
    int row = blockIdx.x;
    int b = row >> 10;
    float4 xv = *(const float4*)(g_h1 + (size_t)row * DD + threadIdx.x * 4);
    float mu, rstd;
    row_stats(xv, mu, rstd, red);
    int d = threadIdx.x * 4;
    float4 g  = *(const float4*)(ln_g + d);
    float4 lb = *(const float4*)(ln_b + d);
    float4 ga = *(const float4*)(g_gamma + b * DD + d);
    float4 be = *(const float4*)(g_beta  + b * DD + d);
    float4 y;
    y.x = fmaf(ga.x, fmaf((xv.x - mu) * rstd, g.x, lb.x), be.x) + xv.x;
    y.y = fmaf(ga.y, fmaf((xv.y - mu) * rstd, g.y, lb.y), be.y) + xv.y;
    y.z = fmaf(ga.z, fmaf((xv.z - mu) * rstd, g.z, lb.z), be.z) + xv.z;
    y.w = fmaf(ga.w, fmaf((xv.w - mu) * rstd, g.w, lb.w), be.w) + xv.w;
    *(float4*)&out[(size_t)row * DD + d] = y;
}

// =====================================================================
extern "C" void kernel_launch(void* const* d_in, const int* in_sizes, int n_in,
                              void* d_out, int out_size)
{
    (void)in_sizes; (void)n_in; (void)out_size;
    const float* hidden = (const float*)d_in[0];
    const float* w      = (const float*)d_in[1];
    const float* ln_g   = (const float*)d_in[2];
    const float* ln_b   = (const float*)d_in[3];
    const float* Wg     = (const float*)d_in[4];
    const float* bg     = (const float*)d_in[5];
    const float* Wb     = (const float*)d_in[6];
    const float* bb     = (const float*)d_in[7];
    const float* Wqkv   = (const float*)d_in[8];
    const float* bqkv   = (const float*)d_in[9];
    const float* Wp     = (const float*)d_in[10];
    const float* bp     = (const float*)d_in[11];
    float* out = (float*)d_out;

    cudaFuncSetAttribute(mm_bf<1>, cudaFuncAttributeMaxDynamicSharedMemorySize, MM_DSMEM);
    cudaFuncSetAttribute(mm_bf<0>, cudaFuncAttributeMaxDynamicSharedMemorySize, MM_DSMEM);
    cudaFuncSetAttribute(attn_bf, cudaFuncAttributeMaxDynamicSharedMemorySize, AT_DSMEM);

    prep_kernel<<<4608, 256>>>(Wqkv, Wp, w, Wg, bg, Wb, bb);
    sln1_kernel<<<ROWS, 256>>>(hidden, ln_g, ln_b);
    mm_bf<1><<<dim3(QKVN / 128, ROWS / 128), 256, MM_DSMEM>>>(bqkv, hidden);
    attn_bf<<<dim3(NN / 128, BB * HH), 256, AT_DSMEM>>>();
    mm_bf<0><<<dim3(DD / 128, ROWS / 128), 256, MM_DSMEM>>>(bp, hidden);
    sln2_kernel<<<ROWS, 256>>>(ln_g, ln_b, out);
}